// round 10
// baseline (speedup 1.0000x reference)
#include <cuda_runtime.h>
#include <cuda_bf16.h>
#include <cstdint>

// Problem constants (match reference)
#define NN 100000      // nodes
#define DD 128         // feature dim
#define EE 200000      // edges per etype
#define ET 3           // etypes
#define NL 3           // layers
#define BN_EPS 1e-5f
#define PL (NN * DD)   // plane size (elements)

#define NTILE 782      // ceil(NN/128)
#define GRID_MM 148

#define SCAN_TOT (ET * NN)   // 300000
#define SCAN_BLK 1024
#define SCAN_NB  ((SCAN_TOT + SCAN_BLK - 1) / SCAN_BLK)   // 293

// ---------------- device scratch (no allocs allowed) ----------------
__device__ float g_preA[(size_t)PL];
__device__ float g_preB[(size_t)PL];
__device__ int   g_cnt[SCAN_TOT];
__device__ float g_inv[SCAN_TOT];
__device__ int   g_off[SCAN_TOT + 1];
__device__ int   g_bsum[SCAN_NB];
__device__ int   g_csr[ET * EE];
__device__ float g_stats[NL * 2 * DD];
__device__ __nv_bfloat16 g_wbf[(size_t)NL * ET * 2 * 2 * DD * DD]; // [l][e][mat][prec][n][k]

// ---------------- helpers ----------------
__device__ __forceinline__ void split2(float a, float b, uint32_t& hi, uint32_t& lo) {
    asm("cvt.rn.bf16x2.f32 %0, %1, %2;" : "=r"(hi) : "f"(b), "f"(a));
    float ra = a - __uint_as_float(hi << 16);
    float rb = b - __uint_as_float(hi & 0xFFFF0000u);
    asm("cvt.rn.bf16x2.f32 %0, %1, %2;" : "=r"(lo) : "f"(rb), "f"(ra));
}
__device__ __forceinline__ uint32_t smem_u32(const void* p) {
    uint32_t a;
    asm("{ .reg .u64 t; cvta.to.shared.u64 t, %1; cvt.u32.u64 %0, t; }" : "=r"(a) : "l"(p));
    return a;
}
__device__ __forceinline__ void cpa16(uint32_t dst, const void* src) {
    asm volatile("cp.async.cg.shared.global [%0], [%1], 16;"
                 :: "r"(dst), "l"(src) : "memory");
}
#define CPA_COMMIT() asm volatile("cp.async.commit_group;" ::: "memory")
#define CPA_WAIT1()  asm volatile("cp.async.wait_group 1;" ::: "memory")

#define LDSM4(rg, addr) \
    asm volatile("ldmatrix.sync.aligned.m8n8.x4.shared.b16 {%0,%1,%2,%3}, [%4];" \
                 : "=r"((rg)[0]), "=r"((rg)[1]), "=r"((rg)[2]), "=r"((rg)[3]) : "r"(addr))
#define MMA16816(d, a, b0, b1) \
    asm volatile("mma.sync.aligned.m16n8k16.row.col.f32.bf16.bf16.f32 " \
                 "{%0,%1,%2,%3}, {%4,%5,%6,%7}, {%8,%9}, {%0,%1,%2,%3};" \
                 : "+f"((d)[0]), "+f"((d)[1]), "+f"((d)[2]), "+f"((d)[3]) \
                 : "r"((a)[0]), "r"((a)[1]), "r"((a)[2]), "r"((a)[3]), "r"(b0), "r"(b1))

// swizzled smem chunk offset: row stride 256B, 16B chunks XOR'd with row&7
#define CHOFF(row, chunk) ((uint32_t)((row) * 256 + ((((chunk) ^ ((row) & 7))) << 4)))

// ---------------- small kernels ----------------
__global__ void zero_f4(float4* __restrict__ p, int n4) {
    int i = blockIdx.x * blockDim.x + threadIdx.x;
    int stride = gridDim.x * blockDim.x;
    float4 z = make_float4(0.f, 0.f, 0.f, 0.f);
    for (; i < n4; i += stride) p[i] = z;
}

__global__ void count_deg(const int* __restrict__ dst, int* __restrict__ cnt, int total, int E) {
    int i = blockIdx.x * blockDim.x + threadIdx.x;
    if (i >= total) return;
    int e = i / E;
    atomicAdd(&cnt[e * NN + dst[i]], 1);
}

__global__ void make_inv(const int* __restrict__ cnt, float* __restrict__ inv, int total) {
    int i = blockIdx.x * blockDim.x + threadIdx.x;
    if (i >= total) return;
    inv[i] = 1.0f / fmaxf((float)cnt[i], 1.0f);
}

__global__ void scan1(const int* __restrict__ cnt, int* __restrict__ off, int* __restrict__ bsum) {
    __shared__ int sm[SCAN_BLK];
    int t = threadIdx.x, b = blockIdx.x;
    int i = b * SCAN_BLK + t;
    int v = (i < SCAN_TOT) ? cnt[i] : 0;
    sm[t] = v;
    __syncthreads();
    for (int d = 1; d < SCAN_BLK; d <<= 1) {
        int x = (t >= d) ? sm[t - d] : 0;
        __syncthreads();
        sm[t] += x;
        __syncthreads();
    }
    if (i < SCAN_TOT) off[i] = sm[t] - v;
    if (t == SCAN_BLK - 1) bsum[b] = sm[t];
}

__global__ void scan2(int* __restrict__ bsum) {
    __shared__ int sm[512];
    int t = threadIdx.x;
    int v = (t < SCAN_NB) ? bsum[t] : 0;
    sm[t] = v;
    __syncthreads();
    for (int d = 1; d < 512; d <<= 1) {
        int x = (t >= d) ? sm[t - d] : 0;
        __syncthreads();
        sm[t] += x;
        __syncthreads();
    }
    if (t < SCAN_NB) bsum[t] = sm[t] - v;
}

__global__ void scan3(int* __restrict__ off, const int* __restrict__ bsum) {
    int i = blockIdx.x * blockDim.x + threadIdx.x;
    if (i < SCAN_TOT) off[i] += bsum[i / SCAN_BLK];
    if (i == 0) off[SCAN_TOT] = ET * EE;
}

__global__ void fill_csr(const int* __restrict__ src, const int* __restrict__ dst,
                         const int* __restrict__ off, int* __restrict__ cursor,
                         int* __restrict__ csr, int total, int E) {
    int i = blockIdx.x * blockDim.x + threadIdx.x;
    if (i >= total) return;
    int e = i / E;
    int idx = e * NN + dst[i];
    int pos = off[idx] + atomicAdd(&cursor[idx], 1);
    csr[pos] = src[i];
}

// weights -> transposed bf16 hi/lo, once per launch
__global__ void prep_weights(const float* __restrict__ Ws, const float* __restrict__ Wn,
                             __nv_bfloat16* __restrict__ out) {
    int i = blockIdx.x * blockDim.x + threadIdx.x;
    const int total = NL * ET * 2 * DD * DD;
    if (i >= total) return;
    int k  = i & 127;
    int n  = (i >> 7) & 127;
    int m  = (i >> 14) & 1;
    int le = i >> 15;
    const float* W = (m == 0 ? Ws : Wn) + (size_t)le * DD * DD;
    float x = W[k * DD + n];          // W[k][n] -> Bt[n][k]
    __nv_bfloat16 h = __float2bfloat16(x);
    float r = x - __bfloat162float(h);
    size_t base = (size_t)((le * 2 + m) * 2) * DD * DD;
    out[base + n * DD + k]           = h;
    out[base + DD * DD + n * DD + k] = __float2bfloat16(r);
}

// final BN apply -> d_out
__global__ void bn_apply(const float* __restrict__ x, const float* __restrict__ stats,
                         const float* __restrict__ gamma, const float* __restrict__ beta,
                         float* __restrict__ y, int N) {
    int col = threadIdx.x;
    float invN = 1.0f / (float)N;
    float mu  = stats[col] * invN;
    float var = stats[DD + col] * invN - mu * mu;
    float sc  = gamma[col] * rsqrtf(var + BN_EPS);
    float sh  = beta[col] - mu * sc;
    for (int r = blockIdx.x; r < N; r += gridDim.x) {
        size_t idx = (size_t)r * DD + col;
        y[idx] = x[idx] * sc + sh;
    }
}

// ---------------- fully fused per-layer kernel ----------------
// smem: bias 1536, affine 1024, self A 64KB, neigh A 64KB, B 3x32KB
#define SM_BIAS 0
#define SM_AFF  1536
#define SM_SELF 2560
#define SM_AN   (SM_SELF + 65536)      // 68096
#define SM_B    (SM_AN + 65536)        // 133632
#define SMEM_TOTAL (SM_B + 3 * 32768)  // 231936

extern __shared__ __align__(1024) char dsm[];

// B stage: one 32KB piece (128 n-rows x 128 k, hi or lo)
__device__ __forceinline__ void stageB(uint32_t dstbase, const __nv_bfloat16* __restrict__ g,
                                       int tid) {
#pragma unroll
    for (int p = 0; p < 4; ++p) {
        int c = tid + p * 512;
        int row = c >> 4;
        int ch  = c & 15;
        cpa16(dstbase + CHOFF(row, ch), g + (size_t)row * DD + ch * 8);
    }
}

// self A tile: contiguous rows of hsrc, BN affine, split -> swizzled smem hi/lo
__device__ __forceinline__ void self_convert(char* __restrict__ dst,
                                             const float* __restrict__ hsrc,
                                             const float* __restrict__ scS,
                                             const float* __restrict__ shS,
                                             int blockRow, int w, int lane) {
    float4 sc = *(const float4*)(scS + lane * 4);
    float4 sh = *(const float4*)(shS + lane * 4);
#pragma unroll 2
    for (int r8 = 0; r8 < 8; ++r8) {
        int r = w * 8 + r8;
        int rg = blockRow + r;
        float a0 = 0.f, a1 = 0.f, a2 = 0.f, a3 = 0.f;
        if (rg < NN) {
            float4 v = *(const float4*)(hsrc + (size_t)rg * DD + lane * 4);
            a0 = v.x * sc.x + sh.x;
            a1 = v.y * sc.y + sh.y;
            a2 = v.z * sc.z + sh.z;
            a3 = v.w * sc.w + sh.w;
        }
        uint32_t hi0, lo0, hi1, lo1;
        split2(a0, a1, hi0, lo0);
        split2(a2, a3, hi1, lo1);
        uint32_t o = (uint32_t)r * 256 + ((((lane >> 1) ^ (r & 7))) << 4) + (lane & 1) * 8;
        *(uint2*)(dst + o)         = make_uint2(hi0, hi1);
        *(uint2*)(dst + 32768 + o) = make_uint2(lo0, lo1);
    }
}

// gather-mean for one etype's 128-node tile, BN affine, split -> swizzled smem hi/lo
__device__ __forceinline__ void gather_tile(char* __restrict__ dst,
                                            const float* __restrict__ hsrc,
                                            const int* __restrict__ csr,
                                            const int* __restrict__ off,
                                            const float* __restrict__ inv,
                                            const float* __restrict__ scS,
                                            const float* __restrict__ shS,
                                            int e, int blockRow, int w, int lane) {
    float4 sc = *(const float4*)(scS + lane * 4);
    float4 sh = *(const float4*)(shS + lane * 4);
#pragma unroll 1
    for (int r8 = 0; r8 < 8; ++r8) {
        int r = w * 8 + r8;
        int node = blockRow + r;
        float a0 = 0.f, a1 = 0.f, a2 = 0.f, a3 = 0.f;
        float m = 0.f, has = 0.f;
        if (node < NN) {
            int idx = e * NN + node;
            int beg = off[idx], end = off[idx + 1];
            int j = beg;
            for (; j + 1 < end; j += 2) {
                int s0 = csr[j], s1 = csr[j + 1];
                float4 v0 = *(const float4*)(hsrc + (size_t)s0 * DD + lane * 4);
                float4 v1 = *(const float4*)(hsrc + (size_t)s1 * DD + lane * 4);
                a0 += v0.x + v1.x; a1 += v0.y + v1.y;
                a2 += v0.z + v1.z; a3 += v0.w + v1.w;
            }
            if (j < end) {
                int s = csr[j];
                float4 v = *(const float4*)(hsrc + (size_t)s * DD + lane * 4);
                a0 += v.x; a1 += v.y; a2 += v.z; a3 += v.w;
            }
            m = inv[idx];
            has = (end > beg) ? 1.0f : 0.0f;
        }
        a0 = a0 * m * sc.x + sh.x * has;
        a1 = a1 * m * sc.y + sh.y * has;
        a2 = a2 * m * sc.z + sh.z * has;
        a3 = a3 * m * sc.w + sh.w * has;
        uint32_t hi0, lo0, hi1, lo1;
        split2(a0, a1, hi0, lo0);
        split2(a2, a3, hi1, lo1);
        uint32_t o = (uint32_t)r * 256 + ((((lane >> 1) ^ (r & 7))) << 4) + (lane & 1) * 8;
        *(uint2*)(dst + o)         = make_uint2(hi0, hi1);
        *(uint2*)(dst + 32768 + o) = make_uint2(lo0, lo1);
    }
}

__device__ __forceinline__ void combo(uint32_t Abase, uint32_t Bbase,
                                      float acc[2][4][4], int lane, int wm, int wn) {
    int sub = lane >> 3, r = lane & 7;
    int arow0 = wm * 32 + r + (sub & 1) * 8;
    int aco = sub >> 1;
    int brow0 = wn * 32 + r + (sub >> 1) * 8;
    int bco = sub & 1;
#pragma unroll
    for (int k16 = 0; k16 < 8; ++k16) {
        uint32_t a[2][4];
#pragma unroll
        for (int mf = 0; mf < 2; ++mf) {
            int row = arow0 + mf * 16;
            LDSM4(a[mf], Abase + (uint32_t)(row * 256) + ((((k16 * 2 + aco) ^ (row & 7))) << 4));
        }
        uint32_t b[2][4];
#pragma unroll
        for (int n16 = 0; n16 < 2; ++n16) {
            int row = brow0 + n16 * 16;
            LDSM4(b[n16], Bbase + (uint32_t)(row * 256) + ((((k16 * 2 + bco) ^ (row & 7))) << 4));
        }
#pragma unroll
        for (int mf = 0; mf < 2; ++mf)
#pragma unroll
            for (int n16 = 0; n16 < 2; ++n16) {
                MMA16816(acc[mf][2 * n16],     a[mf], b[n16][0], b[n16][1]);
                MMA16816(acc[mf][2 * n16 + 1], a[mf], b[n16][2], b[n16][3]);
            }
    }
}

__global__ void __launch_bounds__(512, 1)
mm_fused(const float* __restrict__ hsrc, const int* __restrict__ csr,
         const int* __restrict__ off, const float* __restrict__ inv,
         const __nv_bfloat16* __restrict__ wbf_l, const float* __restrict__ bias_l,
         const float* __restrict__ stP, const float* __restrict__ gammaP,
         const float* __restrict__ betaP, int useBN,
         float* __restrict__ preOut, float* __restrict__ stats, int doRelu) {
    int tid = threadIdx.x;
    int lane = tid & 31;
    int w = tid >> 5;
    int wm = w & 3, wn = w >> 2;

    float* biasS = (float*)(dsm + SM_BIAS);
    float* scS = (float*)(dsm + SM_AFF);
    float* shS = scS + DD;
    if (tid < ET * DD) biasS[tid] = bias_l[tid];
    if (tid < DD) {
        float s = 1.f, hh = 0.f;
        if (useBN) {
            const float invN = 1.0f / (float)NN;
            float mu = stP[tid] * invN;
            float var = stP[DD + tid] * invN - mu * mu;
            s = gammaP[tid] * rsqrtf(var + BN_EPS);
            hh = betaP[tid] - mu * s;
        }
        scS[tid] = s;
        shS[tid] = hh;
    }
    __syncthreads();

    uint32_t sb = smem_u32(dsm);
    uint32_t SELFa = sb + SM_SELF;
    uint32_t ANa   = sb + SM_AN;
    uint32_t Bb[3] = {sb + SM_B, sb + SM_B + 32768, sb + SM_B + 2 * 32768};

    for (int tile = blockIdx.x; tile < NTILE; tile += gridDim.x) {
        int blockRow = tile * 128;

        // B prologue: pieces 0,1,2 (piece i = wbf_l + i*16384, i = 2*pass + prec)
        stageB(Bb[0], wbf_l, tid);                 CPA_COMMIT();
        stageB(Bb[1], wbf_l + 16384, tid);         CPA_COMMIT();
        stageB(Bb[2], wbf_l + 2 * 16384, tid);     CPA_COMMIT();

        // produce A tiles while B pieces fly
        self_convert(dsm + SM_SELF, hsrc, scS, shS, blockRow, w, lane);
        gather_tile(dsm + SM_AN, hsrc, csr, off, inv, scS, shS, 0, blockRow, w, lane);

        float sum[2][4][4];
#pragma unroll
        for (int mf = 0; mf < 2; ++mf)
#pragma unroll
            for (int nb = 0; nb < 4; ++nb)
#pragma unroll
                for (int q = 0; q < 4; ++q) sum[mf][nb][q] = 0.f;

        float acc[2][4][4];

#pragma unroll 1
        for (int q = 0; q < 6; ++q) {
            int e = q >> 1;
            uint32_t Acur = (q & 1) ? ANa : SELFa;
            int bh = (2 * q) % 3, bl = (2 * q + 1) % 3;

            CPA_WAIT1();          // pieces <= 2q+1 complete (only newest may be in flight)
            __syncthreads();      // cross-thread visibility for B pieces + A smem

            if (!(q & 1)) {
#pragma unroll
                for (int mf = 0; mf < 2; ++mf)
#pragma unroll
                    for (int nb = 0; nb < 4; ++nb)
#pragma unroll
                        for (int p2 = 0; p2 < 4; ++p2) acc[mf][nb][p2] = 0.f;
            }

            combo(Acur,         Bb[bh], acc, lane, wm, wn);   // Ahi * Bhi
            combo(Acur + 32768, Bb[bh], acc, lane, wm, wn);   // Alo * Bhi
            __syncthreads();                                   // Bhi buffer free
            if (2 * q + 3 < 12) {
                stageB(Bb[(2 * q + 3) % 3], wbf_l + (size_t)(2 * q + 3) * 16384, tid);
                CPA_COMMIT();
            }
            combo(Acur, Bb[bl], acc, lane, wm, wn);           // Ahi * Blo
            __syncthreads();                                   // Blo buffer + AN free
            if (2 * q + 4 < 12) {
                stageB(Bb[(2 * q + 4) % 3], wbf_l + (size_t)(2 * q + 4) * 16384, tid);
                CPA_COMMIT();
            }

            if (q & 1) {
                // per-etype epilogue: bias + relu + fold into sum
#pragma unroll
                for (int nb = 0; nb < 4; ++nb) {
                    float2 bb = *(const float2*)(biasS + e * DD + wn * 32 +
                                                 nb * 8 + (lane & 3) * 2);
#pragma unroll
                    for (int mf = 0; mf < 2; ++mf) {
                        float v0 = acc[mf][nb][0] + bb.x;
                        float v1 = acc[mf][nb][1] + bb.y;
                        float v2 = acc[mf][nb][2] + bb.x;
                        float v3 = acc[mf][nb][3] + bb.y;
                        if (doRelu) {
                            v0 = fmaxf(v0, 0.f); v1 = fmaxf(v1, 0.f);
                            v2 = fmaxf(v2, 0.f); v3 = fmaxf(v3, 0.f);
                        }
                        sum[mf][nb][0] += v0; sum[mf][nb][1] += v1;
                        sum[mf][nb][2] += v2; sum[mf][nb][3] += v3;
                    }
                }
                if (e < 2)
                    gather_tile(dsm + SM_AN, hsrc, csr, off, inv, scS, shS,
                                e + 1, blockRow, w, lane);
            }
        }

        // write sum -> preOut, fused BN column stats
        float cs[4][2], cq[4][2];
#pragma unroll
        for (int nb = 0; nb < 4; ++nb) {
            cs[nb][0] = cs[nb][1] = 0.f;
            cq[nb][0] = cq[nb][1] = 0.f;
        }
#pragma unroll
        for (int mf = 0; mf < 2; ++mf) {
            int row0 = blockRow + wm * 32 + mf * 16 + (lane >> 2);
            int row1 = row0 + 8;
#pragma unroll
            for (int nb = 0; nb < 4; ++nb) {
                int col = wn * 32 + nb * 8 + (lane & 3) * 2;
                if (row0 < NN) {
                    float v0 = sum[mf][nb][0], v1 = sum[mf][nb][1];
                    *(float2*)(preOut + (size_t)row0 * DD + col) = make_float2(v0, v1);
                    cs[nb][0] += v0; cq[nb][0] += v0 * v0;
                    cs[nb][1] += v1; cq[nb][1] += v1 * v1;
                }
                if (row1 < NN) {
                    float v2 = sum[mf][nb][2], v3 = sum[mf][nb][3];
                    *(float2*)(preOut + (size_t)row1 * DD + col) = make_float2(v2, v3);
                    cs[nb][0] += v2; cq[nb][0] += v2 * v2;
                    cs[nb][1] += v3; cq[nb][1] += v3 * v3;
                }
            }
        }
#pragma unroll
        for (int m = 4; m <= 16; m <<= 1) {
#pragma unroll
            for (int nb = 0; nb < 4; ++nb) {
                cs[nb][0] += __shfl_xor_sync(0xffffffffu, cs[nb][0], m);
                cs[nb][1] += __shfl_xor_sync(0xffffffffu, cs[nb][1], m);
                cq[nb][0] += __shfl_xor_sync(0xffffffffu, cq[nb][0], m);
                cq[nb][1] += __shfl_xor_sync(0xffffffffu, cq[nb][1], m);
            }
        }
        if (lane < 4) {
#pragma unroll
            for (int nb = 0; nb < 4; ++nb) {
                int col = wn * 32 + nb * 8 + lane * 2;
                atomicAdd(&stats[col],          cs[nb][0]);
                atomicAdd(&stats[col + 1],      cs[nb][1]);
                atomicAdd(&stats[DD + col],     cq[nb][0]);
                atomicAdd(&stats[DD + col + 1], cq[nb][1]);
            }
        }
        // final sync of pass loop already ordered all smem reads before next tile's stages
    }
}

// ---------------- launch ----------------
extern "C" void kernel_launch(void* const* d_in, const int* in_sizes, int n_in,
                              void* d_out, int out_size) {
    const float* feat  = (const float*)d_in[0];
    const int*   src   = (const int*)d_in[1];
    const int*   dst   = (const int*)d_in[2];
    const float* Wself = (const float*)d_in[3];
    const float* Wngh  = (const float*)d_in[4];
    const float* bvec  = (const float*)d_in[5];
    const float* gamma = (const float*)d_in[6];
    const float* beta  = (const float*)d_in[7];

    float *preA, *preB, *inv, *stats;
    int *cnt, *off, *bsum, *csr;
    __nv_bfloat16* wbf;
    cudaGetSymbolAddress((void**)&preA,  g_preA);
    cudaGetSymbolAddress((void**)&preB,  g_preB);
    cudaGetSymbolAddress((void**)&cnt,   g_cnt);
    cudaGetSymbolAddress((void**)&inv,   g_inv);
    cudaGetSymbolAddress((void**)&off,   g_off);
    cudaGetSymbolAddress((void**)&bsum,  g_bsum);
    cudaGetSymbolAddress((void**)&csr,   g_csr);
    cudaGetSymbolAddress((void**)&stats, g_stats);
    cudaGetSymbolAddress((void**)&wbf,   g_wbf);

    cudaFuncSetAttribute(mm_fused, cudaFuncAttributeMaxDynamicSharedMemorySize, SMEM_TOTAL);

    const int totE = ET * EE;

    // ---- CSR build + one-time prep (every launch; deterministic) ----
    zero_f4<<<1024, 256>>>((float4*)cnt, SCAN_TOT / 4);
    count_deg<<<(totE + 255) / 256, 256>>>(dst, cnt, totE, EE);
    make_inv<<<(SCAN_TOT + 255) / 256, 256>>>(cnt, inv, SCAN_TOT);
    scan1<<<SCAN_NB, SCAN_BLK>>>(cnt, off, bsum);
    scan2<<<1, 512>>>(bsum);
    scan3<<<(SCAN_TOT + 255) / 256, 256>>>(off, bsum);
    zero_f4<<<1024, 256>>>((float4*)cnt, SCAN_TOT / 4);
    fill_csr<<<(totE + 255) / 256, 256>>>(src, dst, off, cnt, csr, totE, EE);

    prep_weights<<<(NL * ET * 2 * DD * DD + 255) / 256, 256>>>(Wself, Wngh, wbf);
    zero_f4<<<1, 192>>>((float4*)stats, (NL * 2 * DD) / 4);

    for (int l = 0; l < NL; ++l) {
        int doRelu = (l < NL - 1) ? 1 : 0;
        const float* hsrc = (l == 0) ? feat : ((l == 1) ? preA : preB);
        float* out = (l == 1) ? preB : preA;
        const float* stP   = stats + (size_t)((l > 0) ? (l - 1) : 0) * 2 * DD;
        const float* gamP  = gamma + (size_t)((l > 0) ? (l - 1) : 0) * DD;
        const float* betP  = beta  + (size_t)((l > 0) ? (l - 1) : 0) * DD;
        mm_fused<<<GRID_MM, 512, SMEM_TOTAL>>>(
            hsrc, csr, off, inv,
            wbf + (size_t)l * ET * 2 * 2 * DD * DD,
            bvec + (size_t)l * ET * DD,
            stP, gamP, betP, (l > 0) ? 1 : 0,
            out, stats + (size_t)l * 2 * DD, doRelu);
    }
    bn_apply<<<1024, DD>>>(preA, stats + (size_t)(NL - 1) * 2 * DD,
                           gamma + (size_t)(NL - 1) * DD, beta + (size_t)(NL - 1) * DD,
                           (float*)d_out, NN);
}

// round 11
// speedup vs baseline: 1.0292x; 1.0292x over previous
#include <cuda_runtime.h>
#include <cuda_bf16.h>
#include <cstdint>

// Problem constants (match reference)
#define NN 100000      // nodes
#define DD 128         // feature dim
#define EE 200000      // edges per etype
#define ET 3           // etypes
#define NL 3           // layers
#define BN_EPS 1e-5f
#define PL (NN * DD)   // plane size (elements)

#define NTILE 782      // ceil(NN/128)
#define GRID_MM 148

#define SCAN_TOT (ET * NN)   // 300000
#define SCAN_BLK 1024
#define SCAN_NB  ((SCAN_TOT + SCAN_BLK - 1) / SCAN_BLK)   // 293

// ---------------- device scratch (no allocs allowed) ----------------
__device__ float g_preA[(size_t)PL];
__device__ float g_preB[(size_t)PL];
__device__ int   g_cnt[SCAN_TOT];
__device__ float g_inv[SCAN_TOT];
__device__ int   g_off[SCAN_TOT + 1];
__device__ int   g_bsum[SCAN_NB];
__device__ int   g_csr[ET * EE];
__device__ float g_stats[NL * 2 * DD];
__device__ __nv_bfloat16 g_nbf[(size_t)ET * 2 * PL];   // neigh A: per etype [hi][lo]
__device__ __nv_bfloat16 g_wbf[(size_t)NL * ET * 2 * 2 * DD * DD]; // [l][e][mat][prec][n][k]

// ---------------- helpers ----------------
__device__ __forceinline__ void split2(float a, float b, uint32_t& hi, uint32_t& lo) {
    asm("cvt.rn.bf16x2.f32 %0, %1, %2;" : "=r"(hi) : "f"(b), "f"(a));
    float ra = a - __uint_as_float(hi << 16);
    float rb = b - __uint_as_float(hi & 0xFFFF0000u);
    asm("cvt.rn.bf16x2.f32 %0, %1, %2;" : "=r"(lo) : "f"(rb), "f"(ra));
}
__device__ __forceinline__ uint32_t smem_u32(const void* p) {
    uint32_t a;
    asm("{ .reg .u64 t; cvta.to.shared.u64 t, %1; cvt.u32.u64 %0, t; }" : "=r"(a) : "l"(p));
    return a;
}
__device__ __forceinline__ void cpa16(uint32_t dst, const void* src) {
    asm volatile("cp.async.cg.shared.global [%0], [%1], 16;"
                 :: "r"(dst), "l"(src) : "memory");
}
__device__ __forceinline__ void cpa16s(uint32_t dst, const void* src, uint32_t srcsize) {
    asm volatile("cp.async.cg.shared.global [%0], [%1], 16, %2;"
                 :: "r"(dst), "l"(src), "r"(srcsize) : "memory");
}
#define CPA_COMMIT() asm volatile("cp.async.commit_group;" ::: "memory")
#define CPA_WAIT0()  asm volatile("cp.async.wait_group 0;" ::: "memory")
#define CPA_WAIT1()  asm volatile("cp.async.wait_group 1;" ::: "memory")

#define LDSM4(rg, addr) \
    asm volatile("ldmatrix.sync.aligned.m8n8.x4.shared.b16 {%0,%1,%2,%3}, [%4];" \
                 : "=r"((rg)[0]), "=r"((rg)[1]), "=r"((rg)[2]), "=r"((rg)[3]) : "r"(addr))
#define MMA16816(d, a, b0, b1) \
    asm volatile("mma.sync.aligned.m16n8k16.row.col.f32.bf16.bf16.f32 " \
                 "{%0,%1,%2,%3}, {%4,%5,%6,%7}, {%8,%9}, {%0,%1,%2,%3};" \
                 : "+f"((d)[0]), "+f"((d)[1]), "+f"((d)[2]), "+f"((d)[3]) \
                 : "r"((a)[0]), "r"((a)[1]), "r"((a)[2]), "r"((a)[3]), "r"(b0), "r"(b1))

// swizzled smem chunk offset: row stride 256B, 16B chunks XOR'd with row&7
#define CHOFF(row, chunk) ((uint32_t)((row) * 256 + ((((chunk) ^ ((row) & 7))) << 4)))

// ---------------- small kernels ----------------
__global__ void zero_f4(float4* __restrict__ p, int n4) {
    int i = blockIdx.x * blockDim.x + threadIdx.x;
    int stride = gridDim.x * blockDim.x;
    float4 z = make_float4(0.f, 0.f, 0.f, 0.f);
    for (; i < n4; i += stride) p[i] = z;
}

__global__ void count_deg(const int* __restrict__ dst, int* __restrict__ cnt, int total, int E) {
    int i = blockIdx.x * blockDim.x + threadIdx.x;
    if (i >= total) return;
    int e = i / E;
    atomicAdd(&cnt[e * NN + dst[i]], 1);
}

__global__ void make_inv(const int* __restrict__ cnt, float* __restrict__ inv, int total) {
    int i = blockIdx.x * blockDim.x + threadIdx.x;
    if (i >= total) return;
    inv[i] = 1.0f / fmaxf((float)cnt[i], 1.0f);
}

__global__ void scan1(const int* __restrict__ cnt, int* __restrict__ off, int* __restrict__ bsum) {
    __shared__ int sm[SCAN_BLK];
    int t = threadIdx.x, b = blockIdx.x;
    int i = b * SCAN_BLK + t;
    int v = (i < SCAN_TOT) ? cnt[i] : 0;
    sm[t] = v;
    __syncthreads();
    for (int d = 1; d < SCAN_BLK; d <<= 1) {
        int x = (t >= d) ? sm[t - d] : 0;
        __syncthreads();
        sm[t] += x;
        __syncthreads();
    }
    if (i < SCAN_TOT) off[i] = sm[t] - v;
    if (t == SCAN_BLK - 1) bsum[b] = sm[t];
}

__global__ void scan2(int* __restrict__ bsum) {
    __shared__ int sm[512];
    int t = threadIdx.x;
    int v = (t < SCAN_NB) ? bsum[t] : 0;
    sm[t] = v;
    __syncthreads();
    for (int d = 1; d < 512; d <<= 1) {
        int x = (t >= d) ? sm[t - d] : 0;
        __syncthreads();
        sm[t] += x;
        __syncthreads();
    }
    if (t < SCAN_NB) bsum[t] = sm[t] - v;
}

__global__ void scan3(int* __restrict__ off, const int* __restrict__ bsum) {
    int i = blockIdx.x * blockDim.x + threadIdx.x;
    if (i < SCAN_TOT) off[i] += bsum[i / SCAN_BLK];
    if (i == 0) off[SCAN_TOT] = ET * EE;
}

__global__ void fill_csr(const int* __restrict__ src, const int* __restrict__ dst,
                         const int* __restrict__ off, int* __restrict__ cursor,
                         int* __restrict__ csr, int total, int E) {
    int i = blockIdx.x * blockDim.x + threadIdx.x;
    if (i >= total) return;
    int e = i / E;
    int idx = e * NN + dst[i];
    int pos = off[idx] + atomicAdd(&cursor[idx], 1);
    csr[pos] = src[i];
}

// ---- gather-mean with inline BN affine + bf16 split, one warp per (etype,node) ----
__global__ void gather_neigh(const float* __restrict__ hsrc, const int* __restrict__ csr,
                             const int* __restrict__ off, const float* __restrict__ inv,
                             __nv_bfloat16* __restrict__ nbf,
                             const float* __restrict__ stats, const float* __restrict__ gamma,
                             const float* __restrict__ beta, int useBN) {
    int gw = (blockIdx.x * blockDim.x + threadIdx.x) >> 5;
    int lane = threadIdx.x & 31;
    if (gw >= ET * NN) return;
    int e = gw / NN;
    int node = gw - e * NN;

    float sc0 = 1.f, sc1 = 1.f, sc2 = 1.f, sc3 = 1.f;
    float sh0 = 0.f, sh1 = 0.f, sh2 = 0.f, sh3 = 0.f;
    if (useBN) {
        int c = lane * 4;
        const float invN = 1.0f / (float)NN;
        float4 s  = *(const float4*)(stats + c);
        float4 s2 = *(const float4*)(stats + DD + c);
        float4 g  = *(const float4*)(gamma + c);
        float4 bt = *(const float4*)(beta + c);
        float mu, var;
        mu = s.x * invN; var = s2.x * invN - mu * mu;
        sc0 = g.x * rsqrtf(var + BN_EPS); sh0 = bt.x - mu * sc0;
        mu = s.y * invN; var = s2.y * invN - mu * mu;
        sc1 = g.y * rsqrtf(var + BN_EPS); sh1 = bt.y - mu * sc1;
        mu = s.z * invN; var = s2.z * invN - mu * mu;
        sc2 = g.z * rsqrtf(var + BN_EPS); sh2 = bt.z - mu * sc2;
        mu = s.w * invN; var = s2.w * invN - mu * mu;
        sc3 = g.w * rsqrtf(var + BN_EPS); sh3 = bt.w - mu * sc3;
    }

    int beg = off[gw], end = off[gw + 1];
    float a0 = 0.f, a1 = 0.f, a2 = 0.f, a3 = 0.f;
    int j = beg;
    for (; j + 1 < end; j += 2) {
        int s0 = csr[j], s1 = csr[j + 1];
        float4 v0 = *(const float4*)(hsrc + (size_t)s0 * DD + lane * 4);
        float4 v1 = *(const float4*)(hsrc + (size_t)s1 * DD + lane * 4);
        a0 += v0.x + v1.x; a1 += v0.y + v1.y;
        a2 += v0.z + v1.z; a3 += v0.w + v1.w;
    }
    if (j < end) {
        int s = csr[j];
        float4 v = *(const float4*)(hsrc + (size_t)s * DD + lane * 4);
        a0 += v.x; a1 += v.y; a2 += v.z; a3 += v.w;
    }
    float m = inv[gw];
    float has = (end > beg) ? 1.0f : 0.0f;
    a0 = a0 * m * sc0 + sh0 * has;
    a1 = a1 * m * sc1 + sh1 * has;
    a2 = a2 * m * sc2 + sh2 * has;
    a3 = a3 * m * sc3 + sh3 * has;

    uint32_t hi0, lo0, hi1, lo1;
    split2(a0, a1, hi0, lo0);
    split2(a2, a3, hi1, lo1);
    __nv_bfloat16* d = nbf + (size_t)e * 2 * PL;
    size_t p = (size_t)node * DD + lane * 4;
    asm volatile("st.global.cs.v2.b32 [%0], {%1, %2};"
                 :: "l"((void*)(d + p)), "r"(hi0), "r"(hi1) : "memory");
    asm volatile("st.global.cs.v2.b32 [%0], {%1, %2};"
                 :: "l"((void*)(d + PL + p)), "r"(lo0), "r"(lo1) : "memory");
}

// weights -> transposed bf16 hi/lo, once per launch
__global__ void prep_weights(const float* __restrict__ Ws, const float* __restrict__ Wn,
                             __nv_bfloat16* __restrict__ out) {
    int i = blockIdx.x * blockDim.x + threadIdx.x;
    const int total = NL * ET * 2 * DD * DD;
    if (i >= total) return;
    int k  = i & 127;
    int n  = (i >> 7) & 127;
    int m  = (i >> 14) & 1;
    int le = i >> 15;
    const float* W = (m == 0 ? Ws : Wn) + (size_t)le * DD * DD;
    float x = W[k * DD + n];          // W[k][n] -> Bt[n][k]
    __nv_bfloat16 h = __float2bfloat16(x);
    float r = x - __bfloat162float(h);
    size_t base = (size_t)((le * 2 + m) * 2) * DD * DD;
    out[base + n * DD + k]           = h;
    out[base + DD * DD + n * DD + k] = __float2bfloat16(r);
}

// final BN apply -> d_out
__global__ void bn_apply(const float* __restrict__ x, const float* __restrict__ stats,
                         const float* __restrict__ gamma, const float* __restrict__ beta,
                         float* __restrict__ y, int N) {
    int col = threadIdx.x;
    float invN = 1.0f / (float)N;
    float mu  = stats[col] * invN;
    float var = stats[DD + col] * invN - mu * mu;
    float sc  = gamma[col] * rsqrtf(var + BN_EPS);
    float sh  = beta[col] - mu * sc;
    for (int r = blockIdx.x; r < N; r += gridDim.x) {
        size_t idx = (size_t)r * DD + col;
        y[idx] = x[idx] * sc + sh;
    }
}

// ---------------- per-layer GEMM: fused self-convert + async AN staging ----------------
// smem: bias 1536, affine 1024, SELF 64KB, AN 64KB, B 3x32KB
#define SM_BIAS 0
#define SM_AFF  1536
#define SM_SELF 2560
#define SM_AN   (SM_SELF + 65536)
#define SM_B    (SM_AN + 65536)
#define SMEM_TOTAL (SM_B + 3 * 32768)   // 231936

extern __shared__ __align__(1024) char dsm[];

// B stage: one 32KB piece (128 n-rows x 128 k)
__device__ __forceinline__ void stageB(uint32_t dstbase, const __nv_bfloat16* __restrict__ g,
                                       int tid) {
#pragma unroll
    for (int p = 0; p < 4; ++p) {
        int c = tid + p * 512;
        int row = c >> 4;
        int ch  = c & 15;
        cpa16(dstbase + CHOFF(row, ch), g + (size_t)row * DD + ch * 8);
    }
}

// AN stage: bf16 hi/lo planes for one etype (64KB) via cp.async
__device__ __forceinline__ void stageAN(uint32_t dstbase, const __nv_bfloat16* __restrict__ g,
                                        int blockRow, int tid) {
#pragma unroll
    for (int p = 0; p < 8; ++p) {
        int c = tid + p * 512;
        int prec = c >> 11;
        int row  = (c >> 4) & 127;
        int ch   = c & 15;
        int rg = blockRow + row;
        int rs = rg < NN ? rg : 0;
        cpa16s(dstbase + prec * 32768 + CHOFF(row, ch),
               g + (size_t)prec * PL + (size_t)rs * DD + ch * 8, rg < NN ? 16u : 0u);
    }
}

// self A tile: fp32 rows of hsrc, BN affine, split -> swizzled smem hi/lo
__device__ __forceinline__ void self_convert(char* __restrict__ dst,
                                             const float* __restrict__ hsrc,
                                             const float* __restrict__ scS,
                                             const float* __restrict__ shS,
                                             int blockRow, int w, int lane) {
    float4 sc = *(const float4*)(scS + lane * 4);
    float4 sh = *(const float4*)(shS + lane * 4);
#pragma unroll 2
    for (int r8 = 0; r8 < 8; ++r8) {
        int r = w * 8 + r8;
        int rg = blockRow + r;
        float a0 = 0.f, a1 = 0.f, a2 = 0.f, a3 = 0.f;
        if (rg < NN) {
            float4 v = *(const float4*)(hsrc + (size_t)rg * DD + lane * 4);
            a0 = v.x * sc.x + sh.x;
            a1 = v.y * sc.y + sh.y;
            a2 = v.z * sc.z + sh.z;
            a3 = v.w * sc.w + sh.w;
        }
        uint32_t hi0, lo0, hi1, lo1;
        split2(a0, a1, hi0, lo0);
        split2(a2, a3, hi1, lo1);
        uint32_t o = (uint32_t)r * 256 + ((((lane >> 1) ^ (r & 7))) << 4) + (lane & 1) * 8;
        *(uint2*)(dst + o)         = make_uint2(hi0, hi1);
        *(uint2*)(dst + 32768 + o) = make_uint2(lo0, lo1);
    }
}

__device__ __forceinline__ void combo(uint32_t Abase, uint32_t Bbase,
                                      float acc[2][4][4], int lane, int wm, int wn) {
    int sub = lane >> 3, r = lane & 7;
    int arow0 = wm * 32 + r + (sub & 1) * 8;
    int aco = sub >> 1;
    int brow0 = wn * 32 + r + (sub >> 1) * 8;
    int bco = sub & 1;
#pragma unroll
    for (int k16 = 0; k16 < 8; ++k16) {
        uint32_t a[2][4];
#pragma unroll
        for (int mf = 0; mf < 2; ++mf) {
            int row = arow0 + mf * 16;
            LDSM4(a[mf], Abase + (uint32_t)(row * 256) + ((((k16 * 2 + aco) ^ (row & 7))) << 4));
        }
        uint32_t b[2][4];
#pragma unroll
        for (int n16 = 0; n16 < 2; ++n16) {
            int row = brow0 + n16 * 16;
            LDSM4(b[n16], Bbase + (uint32_t)(row * 256) + ((((k16 * 2 + bco) ^ (row & 7))) << 4));
        }
#pragma unroll
        for (int mf = 0; mf < 2; ++mf)
#pragma unroll
            for (int n16 = 0; n16 < 2; ++n16) {
                MMA16816(acc[mf][2 * n16],     a[mf], b[n16][0], b[n16][1]);
                MMA16816(acc[mf][2 * n16 + 1], a[mf], b[n16][2], b[n16][3]);
            }
    }
}

__global__ void __launch_bounds__(512, 1)
mm_fused(const float* __restrict__ hsrc, const __nv_bfloat16* __restrict__ nbf,
         const __nv_bfloat16* __restrict__ wbf_l, const float* __restrict__ bias_l,
         const float* __restrict__ stP, const float* __restrict__ gammaP,
         const float* __restrict__ betaP, int useBN,
         float* __restrict__ preOut, float* __restrict__ stats, int doRelu) {
    int tid = threadIdx.x;
    int lane = tid & 31;
    int w = tid >> 5;
    int wm = w & 3, wn = w >> 2;

    float* biasS = (float*)(dsm + SM_BIAS);
    float* scS = (float*)(dsm + SM_AFF);
    float* shS = scS + DD;
    if (tid < ET * DD) biasS[tid] = bias_l[tid];
    if (tid < DD) {
        float s = 1.f, hh = 0.f;
        if (useBN) {
            const float invN = 1.0f / (float)NN;
            float mu = stP[tid] * invN;
            float var = stP[DD + tid] * invN - mu * mu;
            s = gammaP[tid] * rsqrtf(var + BN_EPS);
            hh = betaP[tid] - mu * s;
        }
        scS[tid] = s;
        shS[tid] = hh;
    }
    __syncthreads();

    uint32_t sb = smem_u32(dsm);
    uint32_t SELFa = sb + SM_SELF;
    uint32_t ANa   = sb + SM_AN;
    uint32_t Bb[3] = {sb + SM_B, sb + SM_B + 32768, sb + SM_B + 2 * 32768};

    for (int tile = blockIdx.x; tile < NTILE; tile += gridDim.x) {
        int blockRow = tile * 128;

        __syncthreads();   // previous tile's combos done before restaging buffers

        // prologue: B pieces 0,1 and AN(e0)
        stageB(Bb[0], wbf_l, tid);              CPA_COMMIT();
        stageB(Bb[1], wbf_l + 16384, tid);      CPA_COMMIT();
        stageAN(ANa, nbf, blockRow, tid);       CPA_COMMIT();
        self_convert(dsm + SM_SELF, hsrc, scS, shS, blockRow, w, lane);

        float sum[2][4][4];
#pragma unroll
        for (int mf = 0; mf < 2; ++mf)
#pragma unroll
            for (int nb = 0; nb < 4; ++nb)
#pragma unroll
                for (int q2 = 0; q2 < 4; ++q2) sum[mf][nb][q2] = 0.f;

        float acc[2][4][4];

#pragma unroll 1
        for (int q = 0; q < 6; ++q) {
            int e = q >> 1;
            uint32_t Acur = (q & 1) ? ANa : SELFa;
            uint32_t Bhi = Bb[(2 * q) % 3];
            uint32_t Blo = Bb[(2 * q + 1) % 3];

            // even passes (except q0) keep the freshly-committed AN stage pending
            if (q == 0 || (q & 1)) { CPA_WAIT0(); } else { CPA_WAIT1(); }
            __syncthreads();

            if (!(q & 1)) {
#pragma unroll
                for (int mf = 0; mf < 2; ++mf)
#pragma unroll
                    for (int nb = 0; nb < 4; ++nb)
#pragma unroll
                        for (int q2 = 0; q2 < 4; ++q2) acc[mf][nb][q2] = 0.f;
            }

            combo(Acur,         Bhi, acc, lane, wm, wn);   // Ahi * Bhi
            combo(Acur + 32768, Bhi, acc, lane, wm, wn);   // Alo * Bhi
            __syncthreads();    // Bhi buffer free (and lo-buffer of pass q-1 free)
            if (q < 5) {
                stageB(Bb[(2 * q + 2) % 3], wbf_l + (size_t)(2 * q + 2) * 16384, tid);
                CPA_COMMIT();
                stageB(Bb[(2 * q) % 3],     wbf_l + (size_t)(2 * q + 3) * 16384, tid);
                CPA_COMMIT();
            }
            combo(Acur, Blo, acc, lane, wm, wn);           // Ahi * Blo

            if (q & 1) {
                __syncthreads();    // AN free: all warps past last AN read
                if (e < 2) {
                    stageAN(ANa, nbf + (size_t)(e + 1) * 2 * PL, blockRow, tid);
                    CPA_COMMIT();
                }
                // per-etype epilogue: bias + relu + fold into sum
#pragma unroll
                for (int nb = 0; nb < 4; ++nb) {
                    float2 bb = *(const float2*)(biasS + e * DD + wn * 32 +
                                                 nb * 8 + (lane & 3) * 2);
#pragma unroll
                    for (int mf = 0; mf < 2; ++mf) {
                        float v0 = acc[mf][nb][0] + bb.x;
                        float v1 = acc[mf][nb][1] + bb.y;
                        float v2 = acc[mf][nb][2] + bb.x;
                        float v3 = acc[mf][nb][3] + bb.y;
                        if (doRelu) {
                            v0 = fmaxf(v0, 0.f); v1 = fmaxf(v1, 0.f);
                            v2 = fmaxf(v2, 0.f); v3 = fmaxf(v3, 0.f);
                        }
                        sum[mf][nb][0] += v0; sum[mf][nb][1] += v1;
                        sum[mf][nb][2] += v2; sum[mf][nb][3] += v3;
                    }
                }
            }
        }

        // write sum -> preOut, fused BN column stats
        float cs[4][2], cq[4][2];
#pragma unroll
        for (int nb = 0; nb < 4; ++nb) {
            cs[nb][0] = cs[nb][1] = 0.f;
            cq[nb][0] = cq[nb][1] = 0.f;
        }
#pragma unroll
        for (int mf = 0; mf < 2; ++mf) {
            int row0 = blockRow + wm * 32 + mf * 16 + (lane >> 2);
            int row1 = row0 + 8;
#pragma unroll
            for (int nb = 0; nb < 4; ++nb) {
                int col = wn * 32 + nb * 8 + (lane & 3) * 2;
                if (row0 < NN) {
                    float v0 = sum[mf][nb][0], v1 = sum[mf][nb][1];
                    *(float2*)(preOut + (size_t)row0 * DD + col) = make_float2(v0, v1);
                    cs[nb][0] += v0; cq[nb][0] += v0 * v0;
                    cs[nb][1] += v1; cq[nb][1] += v1 * v1;
                }
                if (row1 < NN) {
                    float v2 = sum[mf][nb][2], v3 = sum[mf][nb][3];
                    *(float2*)(preOut + (size_t)row1 * DD + col) = make_float2(v2, v3);
                    cs[nb][0] += v2; cq[nb][0] += v2 * v2;
                    cs[nb][1] += v3; cq[nb][1] += v3 * v3;
                }
            }
        }
#pragma unroll
        for (int m = 4; m <= 16; m <<= 1) {
#pragma unroll
            for (int nb = 0; nb < 4; ++nb) {
                cs[nb][0] += __shfl_xor_sync(0xffffffffu, cs[nb][0], m);
                cs[nb][1] += __shfl_xor_sync(0xffffffffu, cs[nb][1], m);
                cq[nb][0] += __shfl_xor_sync(0xffffffffu, cq[nb][0], m);
                cq[nb][1] += __shfl_xor_sync(0xffffffffu, cq[nb][1], m);
            }
        }
        if (lane < 4) {
#pragma unroll
            for (int nb = 0; nb < 4; ++nb) {
                int col = wn * 32 + nb * 8 + lane * 2;
                atomicAdd(&stats[col],          cs[nb][0]);
                atomicAdd(&stats[col + 1],      cs[nb][1]);
                atomicAdd(&stats[DD + col],     cq[nb][0]);
                atomicAdd(&stats[DD + col + 1], cq[nb][1]);
            }
        }
    }
}

// ---------------- launch ----------------
extern "C" void kernel_launch(void* const* d_in, const int* in_sizes, int n_in,
                              void* d_out, int out_size) {
    const float* feat  = (const float*)d_in[0];
    const int*   src   = (const int*)d_in[1];
    const int*   dst   = (const int*)d_in[2];
    const float* Wself = (const float*)d_in[3];
    const float* Wngh  = (const float*)d_in[4];
    const float* bvec  = (const float*)d_in[5];
    const float* gamma = (const float*)d_in[6];
    const float* beta  = (const float*)d_in[7];

    float *preA, *preB, *inv, *stats;
    int *cnt, *off, *bsum, *csr;
    __nv_bfloat16 *wbf, *nbf;
    cudaGetSymbolAddress((void**)&preA,  g_preA);
    cudaGetSymbolAddress((void**)&preB,  g_preB);
    cudaGetSymbolAddress((void**)&cnt,   g_cnt);
    cudaGetSymbolAddress((void**)&inv,   g_inv);
    cudaGetSymbolAddress((void**)&off,   g_off);
    cudaGetSymbolAddress((void**)&bsum,  g_bsum);
    cudaGetSymbolAddress((void**)&csr,   g_csr);
    cudaGetSymbolAddress((void**)&stats, g_stats);
    cudaGetSymbolAddress((void**)&wbf,   g_wbf);
    cudaGetSymbolAddress((void**)&nbf,   g_nbf);

    cudaFuncSetAttribute(mm_fused, cudaFuncAttributeMaxDynamicSharedMemorySize, SMEM_TOTAL);

    const int totE = ET * EE;

    // ---- CSR build + one-time prep (every launch; deterministic) ----
    zero_f4<<<1024, 256>>>((float4*)cnt, SCAN_TOT / 4);
    count_deg<<<(totE + 255) / 256, 256>>>(dst, cnt, totE, EE);
    make_inv<<<(SCAN_TOT + 255) / 256, 256>>>(cnt, inv, SCAN_TOT);
    scan1<<<SCAN_NB, SCAN_BLK>>>(cnt, off, bsum);
    scan2<<<1, 512>>>(bsum);
    scan3<<<(SCAN_TOT + 255) / 256, 256>>>(off, bsum);
    zero_f4<<<1024, 256>>>((float4*)cnt, SCAN_TOT / 4);
    fill_csr<<<(totE + 255) / 256, 256>>>(src, dst, off, cnt, csr, totE, EE);

    prep_weights<<<(NL * ET * 2 * DD * DD + 255) / 256, 256>>>(Wself, Wngh, wbf);
    zero_f4<<<1, 192>>>((float4*)stats, (NL * 2 * DD) / 4);

    for (int l = 0; l < NL; ++l) {
        int doRelu = (l < NL - 1) ? 1 : 0;
        const float* hsrc = (l == 0) ? feat : ((l == 1) ? preA : preB);
        float* out = (l == 1) ? preB : preA;
        int pi = (l > 0) ? (l - 1) : 0;
        const float* stP  = stats + (size_t)pi * 2 * DD;
        const float* gamP = gamma + (size_t)pi * DD;
        const float* betP = beta  + (size_t)pi * DD;
        gather_neigh<<<(SCAN_TOT * 32 + 255) / 256, 256>>>(
            hsrc, csr, off, inv, nbf, stP, gamP, betP, (l > 0) ? 1 : 0);
        mm_fused<<<GRID_MM, 512, SMEM_TOTAL>>>(
            hsrc, nbf,
            wbf + (size_t)l * ET * 2 * 2 * DD * DD,
            bvec + (size_t)l * ET * DD,
            stP, gamP, betP, (l > 0) ? 1 : 0,
            out, stats + (size_t)l * 2 * DD, doRelu);
    }
    bn_apply<<<1024, DD>>>(preA, stats + (size_t)(NL - 1) * 2 * DD,
                           gamma + (size_t)(NL - 1) * DD, beta + (size_t)(NL - 1) * DD,
                           (float*)d_out, NN);
}

// round 12
// speedup vs baseline: 1.4487x; 1.4076x over previous
#include <cuda_runtime.h>
#include <cuda_bf16.h>
#include <cuda_fp16.h>
#include <cstdint>

// Problem constants (match reference)
#define NN 100000      // nodes
#define DD 128         // feature dim
#define EE 200000      // edges per etype
#define ET 3           // etypes
#define NL 3           // layers
#define BN_EPS 1e-5f
#define PL (NN * DD)   // plane size (elements)

#define NTILE 782      // ceil(NN/128)
#define GRID_MM 148

#define SCAN_TOT (ET * NN)   // 300000
#define SCAN_BLK 1024
#define SCAN_NB  ((SCAN_TOT + SCAN_BLK - 1) / SCAN_BLK)   // 293

// wbf: L0 12 pieces, L1 12, L2 8 (self-collapsed); piece = 128n x 128k fp16
#define PIECE_ELEMS 16384
#define WBF_TOTAL (32 * PIECE_ELEMS)

// ---------------- device scratch (no allocs allowed) ----------------
__device__ float g_preA[(size_t)PL];
__device__ float g_preB[(size_t)PL];
__device__ int   g_cnt[SCAN_TOT];
__device__ float g_inv[SCAN_TOT];
__device__ int   g_off[SCAN_TOT + 1];
__device__ int   g_bsum[SCAN_NB];
__device__ int   g_csr[ET * EE];
__device__ float g_stats[NL * 2 * DD];
__device__ __half g_nbf[(size_t)ET * PL];     // neigh A: single fp16 plane per etype
__device__ __half g_wbf[(size_t)WBF_TOTAL];

// ---------------- helpers ----------------
__device__ __forceinline__ uint32_t smem_u32(const void* p) {
    uint32_t a;
    asm("{ .reg .u64 t; cvta.to.shared.u64 t, %1; cvt.u32.u64 %0, t; }" : "=r"(a) : "l"(p));
    return a;
}
__device__ __forceinline__ void cpa16(uint32_t dst, const void* src) {
    asm volatile("cp.async.cg.shared.global [%0], [%1], 16;"
                 :: "r"(dst), "l"(src) : "memory");
}
__device__ __forceinline__ void cpa16s(uint32_t dst, const void* src, uint32_t srcsize) {
    asm volatile("cp.async.cg.shared.global [%0], [%1], 16, %2;"
                 :: "r"(dst), "l"(src), "r"(srcsize) : "memory");
}
#define CPA_COMMIT() asm volatile("cp.async.commit_group;" ::: "memory")
#define CPA_WAIT0()  asm volatile("cp.async.wait_group 0;" ::: "memory")
#define CPA_WAIT1()  asm volatile("cp.async.wait_group 1;" ::: "memory")

#define LDSM4(rg, addr) \
    asm volatile("ldmatrix.sync.aligned.m8n8.x4.shared.b16 {%0,%1,%2,%3}, [%4];" \
                 : "=r"((rg)[0]), "=r"((rg)[1]), "=r"((rg)[2]), "=r"((rg)[3]) : "r"(addr))
#define MMAF16(d, a, b0, b1) \
    asm volatile("mma.sync.aligned.m16n8k16.row.col.f32.f16.f16.f32 " \
                 "{%0,%1,%2,%3}, {%4,%5,%6,%7}, {%8,%9}, {%0,%1,%2,%3};" \
                 : "+f"((d)[0]), "+f"((d)[1]), "+f"((d)[2]), "+f"((d)[3]) \
                 : "r"((a)[0]), "r"((a)[1]), "r"((a)[2]), "r"((a)[3]), "r"(b0), "r"(b1))

// swizzled smem chunk offset: row stride 256B, 16B chunks XOR'd with row&7
#define CHOFF(row, chunk) ((uint32_t)((row) * 256 + ((((chunk) ^ ((row) & 7))) << 4)))

// ---------------- small kernels ----------------
__global__ void zero_f4(float4* __restrict__ p, int n4) {
    int i = blockIdx.x * blockDim.x + threadIdx.x;
    int stride = gridDim.x * blockDim.x;
    float4 z = make_float4(0.f, 0.f, 0.f, 0.f);
    for (; i < n4; i += stride) p[i] = z;
}

__global__ void count_deg(const int* __restrict__ dst, int* __restrict__ cnt, int total, int E) {
    int i = blockIdx.x * blockDim.x + threadIdx.x;
    if (i >= total) return;
    int e = i / E;
    atomicAdd(&cnt[e * NN + dst[i]], 1);
}

__global__ void make_inv(const int* __restrict__ cnt, float* __restrict__ inv, int total) {
    int i = blockIdx.x * blockDim.x + threadIdx.x;
    if (i >= total) return;
    inv[i] = 1.0f / fmaxf((float)cnt[i], 1.0f);
}

__global__ void scan1(const int* __restrict__ cnt, int* __restrict__ off, int* __restrict__ bsum) {
    __shared__ int sm[SCAN_BLK];
    int t = threadIdx.x, b = blockIdx.x;
    int i = b * SCAN_BLK + t;
    int v = (i < SCAN_TOT) ? cnt[i] : 0;
    sm[t] = v;
    __syncthreads();
    for (int d = 1; d < SCAN_BLK; d <<= 1) {
        int x = (t >= d) ? sm[t - d] : 0;
        __syncthreads();
        sm[t] += x;
        __syncthreads();
    }
    if (i < SCAN_TOT) off[i] = sm[t] - v;
    if (t == SCAN_BLK - 1) bsum[b] = sm[t];
}

__global__ void scan2(int* __restrict__ bsum) {
    __shared__ int sm[512];
    int t = threadIdx.x;
    int v = (t < SCAN_NB) ? bsum[t] : 0;
    sm[t] = v;
    __syncthreads();
    for (int d = 1; d < 512; d <<= 1) {
        int x = (t >= d) ? sm[t - d] : 0;
        __syncthreads();
        sm[t] += x;
        __syncthreads();
    }
    if (t < SCAN_NB) bsum[t] = sm[t] - v;
}

__global__ void scan3(int* __restrict__ off, const int* __restrict__ bsum) {
    int i = blockIdx.x * blockDim.x + threadIdx.x;
    if (i < SCAN_TOT) off[i] += bsum[i / SCAN_BLK];
    if (i == 0) off[SCAN_TOT] = ET * EE;
}

__global__ void fill_csr(const int* __restrict__ src, const int* __restrict__ dst,
                         const int* __restrict__ off, int* __restrict__ cursor,
                         int* __restrict__ csr, int total, int E) {
    int i = blockIdx.x * blockDim.x + threadIdx.x;
    if (i >= total) return;
    int e = i / E;
    int idx = e * NN + dst[i];
    int pos = off[idx] + atomicAdd(&cursor[idx], 1);
    csr[pos] = src[i];
}

// ---- gather-mean with inline BN affine -> fp16 plane, one warp per (etype,node) ----
__global__ void gather_neigh(const float* __restrict__ hsrc, const int* __restrict__ csr,
                             const int* __restrict__ off, const float* __restrict__ inv,
                             __half* __restrict__ nbf,
                             const float* __restrict__ stats, const float* __restrict__ gamma,
                             const float* __restrict__ beta, int useBN) {
    int gw = (blockIdx.x * blockDim.x + threadIdx.x) >> 5;
    int lane = threadIdx.x & 31;
    if (gw >= ET * NN) return;
    int e = gw / NN;
    int node = gw - e * NN;

    float sc0 = 1.f, sc1 = 1.f, sc2 = 1.f, sc3 = 1.f;
    float sh0 = 0.f, sh1 = 0.f, sh2 = 0.f, sh3 = 0.f;
    if (useBN) {
        int c = lane * 4;
        const float invN = 1.0f / (float)NN;
        float4 s  = *(const float4*)(stats + c);
        float4 s2 = *(const float4*)(stats + DD + c);
        float4 g  = *(const float4*)(gamma + c);
        float4 bt = *(const float4*)(beta + c);
        float mu, var;
        mu = s.x * invN; var = s2.x * invN - mu * mu;
        sc0 = g.x * rsqrtf(var + BN_EPS); sh0 = bt.x - mu * sc0;
        mu = s.y * invN; var = s2.y * invN - mu * mu;
        sc1 = g.y * rsqrtf(var + BN_EPS); sh1 = bt.y - mu * sc1;
        mu = s.z * invN; var = s2.z * invN - mu * mu;
        sc2 = g.z * rsqrtf(var + BN_EPS); sh2 = bt.z - mu * sc2;
        mu = s.w * invN; var = s2.w * invN - mu * mu;
        sc3 = g.w * rsqrtf(var + BN_EPS); sh3 = bt.w - mu * sc3;
    }

    int beg = off[gw], end = off[gw + 1];
    float a0 = 0.f, a1 = 0.f, a2 = 0.f, a3 = 0.f;
    int j = beg;
    for (; j + 1 < end; j += 2) {
        int s0 = csr[j], s1 = csr[j + 1];
        float4 v0 = *(const float4*)(hsrc + (size_t)s0 * DD + lane * 4);
        float4 v1 = *(const float4*)(hsrc + (size_t)s1 * DD + lane * 4);
        a0 += v0.x + v1.x; a1 += v0.y + v1.y;
        a2 += v0.z + v1.z; a3 += v0.w + v1.w;
    }
    if (j < end) {
        int s = csr[j];
        float4 v = *(const float4*)(hsrc + (size_t)s * DD + lane * 4);
        a0 += v.x; a1 += v.y; a2 += v.z; a3 += v.w;
    }
    float m = inv[gw];
    float has = (end > beg) ? 1.0f : 0.0f;
    a0 = a0 * m * sc0 + sh0 * has;
    a1 = a1 * m * sc1 + sh1 * has;
    a2 = a2 * m * sc2 + sh2 * has;
    a3 = a3 * m * sc3 + sh3 * has;

    __half2 h0 = __floats2half2_rn(a0, a1);
    __half2 h1 = __floats2half2_rn(a2, a3);
    uint32_t u0 = *(uint32_t*)&h0;
    uint32_t u1 = *(uint32_t*)&h1;
    __half* d = nbf + (size_t)e * PL + (size_t)node * DD + lane * 4;
    asm volatile("st.global.cs.v2.b32 [%0], {%1, %2};"
                 :: "l"((void*)d), "r"(u0), "r"(u1) : "memory");
}

// weights -> pass-ordered fp16 hi/lo pieces; layer 2 self collapsed (no relu => exact)
__global__ void prep_weights(const float* __restrict__ Ws, const float* __restrict__ Wn,
                             __half* __restrict__ out) {
    int i = blockIdx.x * blockDim.x + threadIdx.x;
    if (i >= WBF_TOTAL) return;
    int piece = i >> 14;
    int idx = i & 16383;
    int k = idx & 127, n = idx >> 7;
    int l, p;
    if (piece < 12)      { l = 0; p = piece; }
    else if (piece < 24) { l = 1; p = piece - 12; }
    else                 { l = 2; p = piece - 24; }
    int prec = p & 1, pass = p >> 1;
    float val;
    if (l < 2) {
        int e = pass >> 1, mat = pass & 1;
        const float* W = (mat ? Wn : Ws) + (size_t)(l * ET + e) * DD * DD;
        val = W[k * DD + n];
    } else if (pass == 0) {
        const float* W = Ws + (size_t)(2 * ET) * DD * DD;
        val = W[k * DD + n] + W[DD * DD + k * DD + n] + W[2 * DD * DD + k * DD + n];
    } else {
        val = Wn[(size_t)(2 * ET + (pass - 1)) * DD * DD + k * DD + n];
    }
    __half h = __float2half_rn(val);
    if (prec) h = __float2half_rn(val - __half2float(h));
    out[(size_t)piece * PIECE_ELEMS + n * DD + k] = h;
}

// final BN apply -> d_out
__global__ void bn_apply(const float* __restrict__ x, const float* __restrict__ stats,
                         const float* __restrict__ gamma, const float* __restrict__ beta,
                         float* __restrict__ y, int N) {
    int col = threadIdx.x;
    float invN = 1.0f / (float)N;
    float mu  = stats[col] * invN;
    float var = stats[DD + col] * invN - mu * mu;
    float sc  = gamma[col] * rsqrtf(var + BN_EPS);
    float sh  = beta[col] - mu * sc;
    for (int r = blockIdx.x; r < N; r += gridDim.x) {
        size_t idx = (size_t)r * DD + col;
        y[idx] = x[idx] * sc + sh;
    }
}

// ---------------- per-layer GEMM: fp16 2-combo, fused BN-affine + stats ----------------
// smem: bias 1536, affine 1024, SELF 32KB, AN 32KB, B 4x32KB
#define SM_BIAS 0
#define SM_AFF  1536
#define SM_SELF 2560
#define SM_AN   (SM_SELF + 32768)       // 35328
#define SM_B    (SM_AN + 32768)         // 68096
#define SMEM_TOTAL (SM_B + 4 * 32768)   // 199168

extern __shared__ __align__(1024) char dsm[];

// B stage: one 32KB piece (128 n-rows x 128 k fp16)
__device__ __forceinline__ void stageB(uint32_t dstbase, const __half* __restrict__ g,
                                       int tid) {
#pragma unroll
    for (int p = 0; p < 4; ++p) {
        int c = tid + p * 512;
        int row = c >> 4;
        int ch  = c & 15;
        cpa16(dstbase + CHOFF(row, ch), g + (size_t)row * DD + ch * 8);
    }
}

// AN stage: one etype's fp16 plane tile (32KB)
__device__ __forceinline__ void stageAN(uint32_t dstbase, const __half* __restrict__ g,
                                        int blockRow, int tid) {
#pragma unroll
    for (int p = 0; p < 4; ++p) {
        int c = tid + p * 512;
        int row = c >> 4;
        int ch  = c & 15;
        int rg = blockRow + row;
        int rs = rg < NN ? rg : 0;
        cpa16s(dstbase + CHOFF(row, ch), g + (size_t)rs * DD + ch * 8, rg < NN ? 16u : 0u);
    }
}

// self A tile: fp32 rows, BN affine, fp16 -> swizzled smem
__device__ __forceinline__ void self_convert(char* __restrict__ dst,
                                             const float* __restrict__ hsrc,
                                             const float* __restrict__ scS,
                                             const float* __restrict__ shS,
                                             int blockRow, int w, int lane) {
    float4 sc = *(const float4*)(scS + lane * 4);
    float4 sh = *(const float4*)(shS + lane * 4);
#pragma unroll 2
    for (int r8 = 0; r8 < 8; ++r8) {
        int r = w * 8 + r8;
        int rg = blockRow + r;
        float a0 = 0.f, a1 = 0.f, a2 = 0.f, a3 = 0.f;
        if (rg < NN) {
            float4 v = *(const float4*)(hsrc + (size_t)rg * DD + lane * 4);
            a0 = v.x * sc.x + sh.x;
            a1 = v.y * sc.y + sh.y;
            a2 = v.z * sc.z + sh.z;
            a3 = v.w * sc.w + sh.w;
        }
        __half2 h0 = __floats2half2_rn(a0, a1);
        __half2 h1 = __floats2half2_rn(a2, a3);
        uint32_t o = (uint32_t)r * 256 + ((((lane >> 1) ^ (r & 7))) << 4) + (lane & 1) * 8;
        *(uint2*)(dst + o) = make_uint2(*(uint32_t*)&h0, *(uint32_t*)&h1);
    }
}

// fused 2-combo pass: acc += A*(Bhi+Blo), A loaded once per k16
__device__ __forceinline__ void combo2(uint32_t Abase, uint32_t BH, uint32_t BL,
                                       float acc[2][4][4], int lane, int wm, int wn) {
    int sub = lane >> 3, r = lane & 7;
    int arow0 = wm * 32 + r + (sub & 1) * 8;
    int aco = sub >> 1;
    int brow0 = wn * 32 + r + (sub >> 1) * 8;
    int bco = sub & 1;
#pragma unroll
    for (int k16 = 0; k16 < 8; ++k16) {
        uint32_t a[2][4];
#pragma unroll
        for (int mf = 0; mf < 2; ++mf) {
            int row = arow0 + mf * 16;
            LDSM4(a[mf], Abase + (uint32_t)(row * 256) + ((((k16 * 2 + aco) ^ (row & 7))) << 4));
        }
        uint32_t bh[2][4], bl[2][4];
#pragma unroll
        for (int n16 = 0; n16 < 2; ++n16) {
            int row = brow0 + n16 * 16;
            uint32_t o = (uint32_t)(row * 256) + ((((k16 * 2 + bco) ^ (row & 7))) << 4);
            LDSM4(bh[n16], BH + o);
            LDSM4(bl[n16], BL + o);
        }
#pragma unroll
        for (int mf = 0; mf < 2; ++mf)
#pragma unroll
            for (int n16 = 0; n16 < 2; ++n16) {
                MMAF16(acc[mf][2 * n16],     a[mf], bh[n16][0], bh[n16][1]);
                MMAF16(acc[mf][2 * n16 + 1], a[mf], bh[n16][2], bh[n16][3]);
                MMAF16(acc[mf][2 * n16],     a[mf], bl[n16][0], bl[n16][1]);
                MMAF16(acc[mf][2 * n16 + 1], a[mf], bl[n16][2], bl[n16][3]);
            }
    }
}

__global__ void __launch_bounds__(512, 1)
mm_fused(const float* __restrict__ hsrc, const __half* __restrict__ nbf,
         const __half* __restrict__ wbf_l, const float* __restrict__ bias_l,
         const float* __restrict__ stP, const float* __restrict__ gammaP,
         const float* __restrict__ betaP, int useBN,
         float* __restrict__ preOut, float* __restrict__ stats, int doRelu) {
    int tid = threadIdx.x;
    int lane = tid & 31;
    int w = tid >> 5;
    int wm = w & 3, wn = w >> 2;

    float* biasS = (float*)(dsm + SM_BIAS);
    float* scS = (float*)(dsm + SM_AFF);
    float* shS = scS + DD;
    if (tid < ET * DD) biasS[tid] = bias_l[tid];
    if (tid < DD) {
        float s = 1.f, hh = 0.f;
        if (useBN) {
            const float invN = 1.0f / (float)NN;
            float mu = stP[tid] * invN;
            float var = stP[DD + tid] * invN - mu * mu;
            s = gammaP[tid] * rsqrtf(var + BN_EPS);
            hh = betaP[tid] - mu * s;
        }
        scS[tid] = s;
        shS[tid] = hh;
    }
    __syncthreads();

    uint32_t sb = smem_u32(dsm);
    uint32_t SELFa = sb + SM_SELF;
    uint32_t ANa   = sb + SM_AN;
    uint32_t Bb[4] = {sb + SM_B, sb + SM_B + 32768, sb + SM_B + 65536, sb + SM_B + 98304};

    const int NP = doRelu ? 6 : 4;

    for (int tile = blockIdx.x; tile < NTILE; tile += gridDim.x) {
        int blockRow = tile * 128;

        __syncthreads();   // previous tile's reads done before restaging

        // prologue: B pieces 0,1 + AN(e0) in one group
        stageB(Bb[0], wbf_l, tid);
        stageB(Bb[1], wbf_l + PIECE_ELEMS, tid);
        stageAN(ANa, nbf, blockRow, tid);
        CPA_COMMIT();
        self_convert(dsm + SM_SELF, hsrc, scS, shS, blockRow, w, lane);

        float sum[2][4][4];
#pragma unroll
        for (int mf = 0; mf < 2; ++mf)
#pragma unroll
            for (int nb = 0; nb < 4; ++nb)
#pragma unroll
                for (int q2 = 0; q2 < 4; ++q2) sum[mf][nb][q2] = 0.f;

        float acc[2][4][4];

#pragma unroll 1
        for (int q = 0; q < NP; ++q) {
            bool isSelf  = doRelu ? ((q & 1) == 0) : (q == 0);
            bool zeroAcc = doRelu ? ((q & 1) == 0) : (q != 1);
            bool fold    = doRelu ? ((q & 1) != 0) : (q >= 1);
            int  eFold   = doRelu ? (q >> 1) : (q - 1);

            if (q > 0) {
                __syncthreads();   // close previous pass before overwriting buffers
                bool prevFold = doRelu ? (((q - 1) & 1) != 0) : ((q - 1) >= 1);
                int ePrev = doRelu ? ((q - 1) >> 1) : (q - 2);
                if (prevFold && ePrev + 1 < ET) {
                    stageAN(ANa, nbf + (size_t)(ePrev + 1) * PL, blockRow, tid);
                    CPA_COMMIT();
                }
            }
            if (2 * q + 2 < 2 * NP) {
                stageB(Bb[(2 * q + 2) & 3], wbf_l + (size_t)(2 * q + 2) * PIECE_ELEMS, tid);
                stageB(Bb[(2 * q + 3) & 3], wbf_l + (size_t)(2 * q + 3) * PIECE_ELEMS, tid);
                CPA_COMMIT();
                CPA_WAIT1();
            } else {
                CPA_WAIT0();
            }
            __syncthreads();

            if (zeroAcc) {
#pragma unroll
                for (int mf = 0; mf < 2; ++mf)
#pragma unroll
                    for (int nb = 0; nb < 4; ++nb)
#pragma unroll
                        for (int q2 = 0; q2 < 4; ++q2) acc[mf][nb][q2] = 0.f;
            }

            combo2(isSelf ? SELFa : ANa, Bb[(2 * q) & 3], Bb[(2 * q + 1) & 3],
                   acc, lane, wm, wn);

            if (fold) {
#pragma unroll
                for (int nb = 0; nb < 4; ++nb) {
                    float2 bb = *(const float2*)(biasS + eFold * DD + wn * 32 +
                                                 nb * 8 + (lane & 3) * 2);
#pragma unroll
                    for (int mf = 0; mf < 2; ++mf) {
                        float v0 = acc[mf][nb][0] + bb.x;
                        float v1 = acc[mf][nb][1] + bb.y;
                        float v2 = acc[mf][nb][2] + bb.x;
                        float v3 = acc[mf][nb][3] + bb.y;
                        if (doRelu) {
                            v0 = fmaxf(v0, 0.f); v1 = fmaxf(v1, 0.f);
                            v2 = fmaxf(v2, 0.f); v3 = fmaxf(v3, 0.f);
                        }
                        sum[mf][nb][0] += v0; sum[mf][nb][1] += v1;
                        sum[mf][nb][2] += v2; sum[mf][nb][3] += v3;
                    }
                }
            }
        }

        // write sum -> preOut, fused BN column stats
        float cs[4][2], cq[4][2];
#pragma unroll
        for (int nb = 0; nb < 4; ++nb) {
            cs[nb][0] = cs[nb][1] = 0.f;
            cq[nb][0] = cq[nb][1] = 0.f;
        }
#pragma unroll
        for (int mf = 0; mf < 2; ++mf) {
            int row0 = blockRow + wm * 32 + mf * 16 + (lane >> 2);
            int row1 = row0 + 8;
#pragma unroll
            for (int nb = 0; nb < 4; ++nb) {
                int col = wn * 32 + nb * 8 + (lane & 3) * 2;
                if (row0 < NN) {
                    float v0 = sum[mf][nb][0], v1 = sum[mf][nb][1];
                    *(float2*)(preOut + (size_t)row0 * DD + col) = make_float2(v0, v1);
                    cs[nb][0] += v0; cq[nb][0] += v0 * v0;
                    cs[nb][1] += v1; cq[nb][1] += v1 * v1;
                }
                if (row1 < NN) {
                    float v2 = sum[mf][nb][2], v3 = sum[mf][nb][3];
                    *(float2*)(preOut + (size_t)row1 * DD + col) = make_float2(v2, v3);
                    cs[nb][0] += v2; cq[nb][0] += v2 * v2;
                    cs[nb][1] += v3; cq[nb][1] += v3 * v3;
                }
            }
        }
#pragma unroll
        for (int m = 4; m <= 16; m <<= 1) {
#pragma unroll
            for (int nb = 0; nb < 4; ++nb) {
                cs[nb][0] += __shfl_xor_sync(0xffffffffu, cs[nb][0], m);
                cs[nb][1] += __shfl_xor_sync(0xffffffffu, cs[nb][1], m);
                cq[nb][0] += __shfl_xor_sync(0xffffffffu, cq[nb][0], m);
                cq[nb][1] += __shfl_xor_sync(0xffffffffu, cq[nb][1], m);
            }
        }
        if (lane < 4) {
#pragma unroll
            for (int nb = 0; nb < 4; ++nb) {
                int col = wn * 32 + nb * 8 + lane * 2;
                atomicAdd(&stats[col],          cs[nb][0]);
                atomicAdd(&stats[col + 1],      cs[nb][1]);
                atomicAdd(&stats[DD + col],     cq[nb][0]);
                atomicAdd(&stats[DD + col + 1], cq[nb][1]);
            }
        }
    }
}

// ---------------- launch ----------------
extern "C" void kernel_launch(void* const* d_in, const int* in_sizes, int n_in,
                              void* d_out, int out_size) {
    const float* feat  = (const float*)d_in[0];
    const int*   src   = (const int*)d_in[1];
    const int*   dst   = (const int*)d_in[2];
    const float* Wself = (const float*)d_in[3];
    const float* Wngh  = (const float*)d_in[4];
    const float* bvec  = (const float*)d_in[5];
    const float* gamma = (const float*)d_in[6];
    const float* beta  = (const float*)d_in[7];

    float *preA, *preB, *inv, *stats;
    int *cnt, *off, *bsum, *csr;
    __half *wbf, *nbf;
    cudaGetSymbolAddress((void**)&preA,  g_preA);
    cudaGetSymbolAddress((void**)&preB,  g_preB);
    cudaGetSymbolAddress((void**)&cnt,   g_cnt);
    cudaGetSymbolAddress((void**)&inv,   g_inv);
    cudaGetSymbolAddress((void**)&off,   g_off);
    cudaGetSymbolAddress((void**)&bsum,  g_bsum);
    cudaGetSymbolAddress((void**)&csr,   g_csr);
    cudaGetSymbolAddress((void**)&stats, g_stats);
    cudaGetSymbolAddress((void**)&wbf,   g_wbf);
    cudaGetSymbolAddress((void**)&nbf,   g_nbf);

    cudaFuncSetAttribute(mm_fused, cudaFuncAttributeMaxDynamicSharedMemorySize, SMEM_TOTAL);

    const int totE = ET * EE;

    // ---- CSR build + one-time prep (every launch; deterministic) ----
    zero_f4<<<1024, 256>>>((float4*)cnt, SCAN_TOT / 4);
    count_deg<<<(totE + 255) / 256, 256>>>(dst, cnt, totE, EE);
    make_inv<<<(SCAN_TOT + 255) / 256, 256>>>(cnt, inv, SCAN_TOT);
    scan1<<<SCAN_NB, SCAN_BLK>>>(cnt, off, bsum);
    scan2<<<1, 512>>>(bsum);
    scan3<<<(SCAN_TOT + 255) / 256, 256>>>(off, bsum);
    zero_f4<<<1024, 256>>>((float4*)cnt, SCAN_TOT / 4);
    fill_csr<<<(totE + 255) / 256, 256>>>(src, dst, off, cnt, csr, totE, EE);

    prep_weights<<<(WBF_TOTAL + 255) / 256, 256>>>(Wself, Wngh, wbf);
    zero_f4<<<1, 192>>>((float4*)stats, (NL * 2 * DD) / 4);

    const size_t wbf_off[NL] = {0, 12 * (size_t)PIECE_ELEMS, 24 * (size_t)PIECE_ELEMS};

    for (int l = 0; l < NL; ++l) {
        int doRelu = (l < NL - 1) ? 1 : 0;
        const float* hsrc = (l == 0) ? feat : ((l == 1) ? preA : preB);
        float* out = (l == 1) ? preB : preA;
        int pi = (l > 0) ? (l - 1) : 0;
        const float* stP  = stats + (size_t)pi * 2 * DD;
        const float* gamP = gamma + (size_t)pi * DD;
        const float* betP = beta  + (size_t)pi * DD;
        gather_neigh<<<(SCAN_TOT * 32 + 255) / 256, 256>>>(
            hsrc, csr, off, inv, nbf, stP, gamP, betP, (l > 0) ? 1 : 0);
        mm_fused<<<GRID_MM, 512, SMEM_TOTAL>>>(
            hsrc, nbf, wbf + wbf_off[l],
            bvec + (size_t)l * ET * DD,
            stP, gamP, betP, (l > 0) ? 1 : 0,
            out, stats + (size_t)l * 2 * DD, doRelu);
    }
    bn_apply<<<1024, DD>>>(preA, stats + (size_t)(NL - 1) * 2 * DD,
                           gamma + (size_t)(NL - 1) * DD, beta + (size_t)(NL - 1) * DD,
                           (float*)d_out, NN);
}